// round 8
// baseline (speedup 1.0000x reference)
#include <cuda_runtime.h>
#include <math.h>
#include <stdint.h>

// ---------------- problem constants ----------------
#define B_   128
#define L_   512
#define H_   336
#define D_   256
#define TXT_ 768
#define K_   16
#define S_   4
#define EMB_ 128
#define SHIFT_ 56            // max(1, H//6)
#define PI_F 3.14159265358979323846f

// scratch (device globals; runtime allocation is forbidden). All 16B-aligned
// because several are accessed through float4*.
__device__ __align__(16) float  g_mu[B_ * K_];
__device__ __align__(16) float  g_r[B_ * K_];
__device__ __align__(16) float  g_s[B_ * H_];                 // y_tir_scalar
__device__ __align__(16) float  g_kn[B_ * K_ * EMB_];         // normalized k_emb
__device__ __align__(16) float  g_ts[B_ * D_];                // enc mean
__device__ __align__(16) float  g_gate[B_ * D_];
__device__ __align__(16) float  g_fpos[(size_t)B_ * H_ * EMB_];
__device__ __align__(16) float  g_invn[B_ * H_];              // 1/(||f_pos row||+1e-8)
__device__ __align__(16) float  g_M[3 * D_ * EMB_];           // combined W_fp shift matrices
__device__ __align__(16) double g_acc[8];  // 0 mse, 1 cot, 2 sum log_softmax, 3 ent, 4 tv

// ---------------- helpers ----------------
__device__ __forceinline__ float softplusf_(float x) {
    return fmaxf(x, 0.f) + log1pf(expf(-fabsf(x)));
}
__device__ __forceinline__ float sigmoidf_(float x) { return 1.f / (1.f + expf(-x)); }

__device__ __forceinline__ float warpReduceSum_(float v) {
#pragma unroll
    for (int o = 16; o; o >>= 1) v += __shfl_xor_sync(0xffffffffu, v, o);
    return v;
}
// blockDim.x == 256, result valid on thread 0
__device__ __forceinline__ float blockReduce256_(float v, float* red) {
    int lane = threadIdx.x & 31, w = threadIdx.x >> 5;
    v = warpReduceSum_(v);
    __syncthreads();
    if (lane == 0) red[w] = v;
    __syncthreads();
    v = 0.f;
    if (w == 0) {
        v = (lane < 8) ? red[lane] : 0.f;
#pragma unroll
        for (int o = 4; o; o >>= 1) v += __shfl_xor_sync(0xffffffffu, v, o);
    }
    __syncthreads();
    return v;
}

// ---------------- kernel: zero accumulators ----------------
__global__ void k_zero() {
    if (threadIdx.x < 8) g_acc[threadIdx.x] = 0.0;
}

// ---------------- kernel: build combined Wfp matrices ----------------
// f_pos[h] = y[h]@M0 + y[h-1]@M1 + y[h-2]@M2  (y[-1]=y[-2]=y[0])
__global__ void k_prep_M(const float* __restrict__ Wfp) {
    int i = blockIdx.x * blockDim.x + threadIdx.x;
    if (i >= D_ * EMB_) return;
    float w0 = Wfp[i];
    float w1 = Wfp[D_ * EMB_ + i];
    float w2 = Wfp[2 * D_ * EMB_ + i];
    g_M[i]                 = w0 + w1 + w2;
    g_M[D_ * EMB_ + i]     = -(w1 + 2.f * w2);
    g_M[2 * D_ * EMB_ + i] = w2;
}

// ---------------- kernel: text2kernels + k_emb + ent/tv ----------------
// grid 128 (one per batch), 128 threads
__global__ void k_text2k(const float* __restrict__ text_emb,
                         const float* __restrict__ W_t2k, const float* __restrict__ b_t2k,
                         const float* __restrict__ W_kemb, const float* __restrict__ b_kemb) {
    int b = blockIdx.x, tid = threadIdx.x;
    __shared__ float temb[TXT_];
    __shared__ float raw[K_ * 7];
    __shared__ float muS[K_], sigS[K_], ampS[K_], swS[K_][S_];
    __shared__ float kap[K_ * H_];
    __shared__ float ksum[K_];
    __shared__ float kemb[K_ * EMB_];
    __shared__ float nrm[K_];
    __shared__ float entv[K_];

    for (int i = tid; i < TXT_; i += 128) temb[i] = text_emb[b * TXT_ + i];
    __syncthreads();

    if (tid < K_ * 7) {
        float acc = b_t2k[tid];
        for (int i = 0; i < TXT_; i++) acc += temb[i] * W_t2k[i * (K_ * 7) + tid];
        raw[tid] = acc;
    }
    __syncthreads();

    if (tid < K_) {
        int k = tid;
        float mu  = sigmoidf_(raw[k * 7 + 0]);
        float sig = softplusf_(raw[k * 7 + 1]) * 0.15f + 1e-3f;
        float amp = softplusf_(raw[k * 7 + 2]);
        float m = raw[k * 7 + 3];
        for (int s = 1; s < S_; s++) m = fmaxf(m, raw[k * 7 + 3 + s]);
        float es[S_], Z = 0.f;
        for (int s = 0; s < S_; s++) { es[s] = expf(raw[k * 7 + 3 + s] - m); Z += es[s]; }
        float ent = 0.f;
        for (int s = 0; s < S_; s++) {
            float sw = es[s] / Z;
            swS[k][s] = sw;
            float swc = fmaxf(sw, 1e-8f);
            ent += swc * logf(swc);
        }
        muS[k] = mu; sigS[k] = sig; ampS[k] = amp; entv[k] = ent;
        g_mu[b * K_ + k] = mu;
    }
    __syncthreads();
    if (tid == 0) {
        float tv = 0.f, es = 0.f;
        for (int k = 1; k < K_; k++) tv += fabsf(muS[k] - muS[k - 1]);
        for (int k = 0; k < K_; k++) es += entv[k];
        atomicAdd(&g_acc[3], (double)es);
        atomicAdd(&g_acc[4], (double)tv);
    }

    // kappa
    for (int i = tid; i < K_ * H_; i += 128) {
        int k = i / H_, h = i % H_;
        float t = (h + 0.5f) / (float)H_;
        float z = (t - muS[k]) / sigS[k];
        float az = fabsf(z);
        float b0 = expf(-0.5f * z * z);
        float b1 = expf(-az);
        float b2 = fmaxf(1.f - az, 0.f);
        float zc = fminf(fmaxf(z, -1.f), 1.f);
        float b3 = (az <= 1.f) ? 0.5f * (1.f + cosf(PI_F * zc)) : 0.f;
        kap[i] = ampS[k] * (b0 * swS[k][0] + b1 * swS[k][1] + b2 * swS[k][2] + b3 * swS[k][3]);
    }
    __syncthreads();

    if (tid < K_) {
        float s = 0.f;
        for (int h = 0; h < H_; h++) s += kap[tid * H_ + h];
        ksum[tid] = s + 1e-6f;
    }
    __syncthreads();
    if (tid < K_) {
        float tot = 0.f;
        for (int k = 0; k < K_; k++) tot += ksum[k];
        g_r[b * K_ + tid] = ksum[tid] / tot;
    }
    for (int h = tid; h < H_; h += 128) {
        float s = 0.f;
#pragma unroll
        for (int k = 0; k < K_; k++) s += kap[k * H_ + h];
        g_s[b * H_ + h] = s;
    }

    // k_emb = kappa @ W_kemb + b_kemb, thread = embedding column
    {
        int e = tid;
        float acc[K_];
#pragma unroll
        for (int k = 0; k < K_; k++) acc[k] = b_kemb[e];
        for (int h = 0; h < H_; h++) {
            float wv = W_kemb[h * EMB_ + e];
#pragma unroll
            for (int k = 0; k < K_; k++) acc[k] += kap[k * H_ + h] * wv;
        }
#pragma unroll
        for (int k = 0; k < K_; k++) kemb[k * EMB_ + e] = acc[k];
    }
    __syncthreads();
    // norms: warp w handles k = 4w..4w+3
    {
        int w = tid >> 5, lane = tid & 31;
        for (int q = 0; q < 4; q++) {
            int k = w * 4 + q;
            float p = 0.f;
#pragma unroll
            for (int j = 0; j < 4; j++) { float v = kemb[k * EMB_ + lane + 32 * j]; p += v * v; }
            p = warpReduceSum_(p);
            if (lane == 0) nrm[k] = sqrtf(p) + 1e-8f;
        }
    }
    __syncthreads();
#pragma unroll
    for (int k = 0; k < K_; k++)
        g_kn[(b * K_ + k) * EMB_ + tid] = kemb[k * EMB_ + tid] / nrm[k];
}

// ---------------- kernel: enc_out mean over L ----------------
__global__ void k_ts(const float* __restrict__ enc) {
    int b = blockIdx.x, d = threadIdx.x;
    const float* p = enc + (size_t)b * L_ * D_ + d;
    float s = 0.f;
#pragma unroll 8
    for (int l = 0; l < L_; l++) s += p[(size_t)l * D_];
    g_ts[b * D_ + d] = s * (1.f / (float)L_);
}

// ---------------- kernel: gate MLP ----------------
#define NBG 4
__global__ void k_gate(const float* __restrict__ text_emb, const float* __restrict__ var_proj,
                       const float* __restrict__ Wg1, const float* __restrict__ bg1,
                       const float* __restrict__ Wg2, const float* __restrict__ bg2) {
    int b0 = blockIdx.x * NBG, tid = threadIdx.x; // 512 threads
    __shared__ float gin[NBG][2 * D_ + TXT_];
    __shared__ float h1[NBG][512];
    for (int bb = 0; bb < NBG; bb++) {
        int b = b0 + bb;
        for (int i = tid; i < D_; i += 512) gin[bb][i] = g_ts[b * D_ + i];
        for (int i = tid; i < TXT_; i += 512) gin[bb][D_ + i] = text_emb[b * TXT_ + i];
        for (int i = tid; i < D_; i += 512) gin[bb][D_ + TXT_ + i] = var_proj[i];
    }
    __syncthreads();
    {
        int j = tid;
        float a[NBG];
#pragma unroll
        for (int bb = 0; bb < NBG; bb++) a[bb] = bg1[j];
        for (int i = 0; i < 2 * D_ + TXT_; i++) {
            float w = Wg1[i * 512 + j];
#pragma unroll
            for (int bb = 0; bb < NBG; bb++) a[bb] += gin[bb][i] * w;
        }
#pragma unroll
        for (int bb = 0; bb < NBG; bb++) h1[bb][j] = fmaxf(a[bb], 0.f);
    }
    __syncthreads();
    if (tid < D_) {
        int d = tid;
        float a[NBG];
#pragma unroll
        for (int bb = 0; bb < NBG; bb++) a[bb] = bg2[d];
        for (int i = 0; i < 512; i++) {
            float w = Wg2[i * D_ + d];
#pragma unroll
            for (int bb = 0; bb < NBG; bb++) a[bb] += h1[bb][i] * w;
        }
#pragma unroll
        for (int bb = 0; bb < NBG; bb++) g_gate[(b0 + bb) * D_ + d] = sigmoidf_(a[bb]);
    }
}

// ---------------- kernel: fused y_tir/gate/mse ----------------
__global__ void k_mse(const float* __restrict__ y_res, const float* __restrict__ y_fut,
                      const float* __restrict__ W_tir, const float* __restrict__ b_tir,
                      const float* __restrict__ var_proj) {
    __shared__ float red[32];
    const int N4 = B_ * H_ * (D_ / 4);
    float local = 0.f;
    for (int i4 = blockIdx.x * blockDim.x + threadIdx.x; i4 < N4; i4 += gridDim.x * blockDim.x) {
        int b = i4 / (H_ * (D_ / 4));
        int rem = i4 % (H_ * (D_ / 4));
        int h = rem / (D_ / 4);
        int d4 = rem % (D_ / 4);
        float4 yr = *(const float4*)&y_res[(size_t)i4 * 4];
        float4 yf = *(const float4*)&y_fut[(size_t)i4 * 4];
        float4 wt = *(const float4*)&W_tir[d4 * 4];
        float4 bt = *(const float4*)&b_tir[d4 * 4];
        float4 vp = *(const float4*)&var_proj[d4 * 4];
        float4 gt = *(const float4*)&g_gate[b * D_ + d4 * 4];
        float s = g_s[b * H_ + h];
        float dx, ytir;
        ytir = (s * wt.x + bt.x) * vp.x; dx = (yr.x + 0.5f * gt.x * (ytir - yr.x)) - yf.x; local += dx * dx;
        ytir = (s * wt.y + bt.y) * vp.y; dx = (yr.y + 0.5f * gt.y * (ytir - yr.y)) - yf.y; local += dx * dx;
        ytir = (s * wt.z + bt.z) * vp.z; dx = (yr.z + 0.5f * gt.z * (ytir - yr.z)) - yf.z; local += dx * dx;
        ytir = (s * wt.w + bt.w) * vp.w; dx = (yr.w + 0.5f * gt.w * (ytir - yr.w)) - yf.w; local += dx * dx;
    }
    float tot = blockReduce256_(local, red);
    if (threadIdx.x == 0) atomicAdd(&g_acc[0], (double)tot);
}

// ---------------- kernel: f_pos GEMM (56 rows x 128 cols per block) ----------------
// ysh region padded to 1920 floats (7680 B) so Msh is 16B-aligned for float4.
#define YSH_PAD 1920
#define FP_SMEM ((YSH_PAD + 3 * 32 * 128) * 4)
__global__ void k_fpos(const float* __restrict__ yf, const float* __restrict__ bfp) {
    extern __shared__ float sm[];
    float* ysh = sm;             // 58 x 33 (row padded), region padded to 1920
    float* Msh = sm + YSH_PAD;   // 3 x 32 x 128, 16B-aligned
    int b = blockIdx.y;
    int h0 = blockIdx.x * 56;
    int tid = threadIdx.x;
    int ct = tid & 31, rt = tid >> 5;
    float acc[7][4];
#pragma unroll
    for (int i = 0; i < 7; i++)
#pragma unroll
        for (int c = 0; c < 4; c++) acc[i][c] = 0.f;

    for (int kc = 0; kc < 8; kc++) {
        const float* ybase = yf + (size_t)b * H_ * D_ + kc * 32;
        for (int i = tid; i < 58 * 32; i += 256) {
            int row = i >> 5, col = i & 31;
            int h = h0 - 2 + row; if (h < 0) h = 0;
            ysh[row * 33 + col] = ybase[(size_t)h * D_ + col];
        }
        const float4* Mg = (const float4*)g_M;
        float4* Ms4 = (float4*)Msh;
        for (int i = tid; i < 3072; i += 256) {
            int j = i >> 10;
            int rr = (i >> 5) & 31;
            int e4 = i & 31;
            Ms4[i] = Mg[j * (D_ * EMB_ / 4) + (kc * 32 + rr) * 32 + e4];
        }
        __syncthreads();
#pragma unroll
        for (int k = 0; k < 32; k++) {
            float4 m0 = *(float4*)&Msh[k * 128 + ct * 4];
            float4 m1 = *(float4*)&Msh[4096 + k * 128 + ct * 4];
            float4 m2 = *(float4*)&Msh[8192 + k * 128 + ct * 4];
#pragma unroll
            for (int i = 0; i < 7; i++) {
                int r = rt + 8 * i;
                float y2 = ysh[(r + 2) * 33 + k];
                float y1 = ysh[(r + 1) * 33 + k];
                float y0 = ysh[r * 33 + k];
                acc[i][0] += y2 * m0.x + y1 * m1.x + y0 * m2.x;
                acc[i][1] += y2 * m0.y + y1 * m1.y + y0 * m2.y;
                acc[i][2] += y2 * m0.z + y1 * m1.z + y0 * m2.z;
                acc[i][3] += y2 * m0.w + y1 * m1.w + y0 * m2.w;
            }
        }
        __syncthreads();
    }
    float4 bt = *(const float4*)&bfp[ct * 4];
#pragma unroll
    for (int i = 0; i < 7; i++) {
        int h = h0 + rt + 8 * i;
        float4 o;
        o.x = acc[i][0] + bt.x;
        o.y = acc[i][1] + bt.y;
        o.z = acc[i][2] + bt.z;
        o.w = acc[i][3] + bt.w;
        float ss = o.x * o.x + o.y * o.y + o.z * o.z + o.w * o.w;
        ss = warpReduceSum_(ss);
        ss = __shfl_sync(0xffffffffu, ss, 0);
        if (ct == 0) g_invn[b * H_ + h] = 1.f / (sqrtf(ss) + 1e-8f);
        *(float4*)&g_fpos[((size_t)(b * H_ + h)) * EMB_ + ct * 4] = o;
    }
}

// ---------------- kernel: per-batch cost/sinkhorn/contrastive ----------------
#define LS_FLOATS (2048 + 5376 + 5376 + 16 * 129 + 16 + 16 + 336 + 16 + 4096 + 16 + 16 + 32)
#define LOSS_SMEM (LS_FLOATS * 4 + 128 * 4)
__global__ void k_loss(const int* __restrict__ perm) {
    int b = blockIdx.x, tid = threadIdx.x; // 256 threads
    extern __shared__ float sm[];
    float* kn   = sm;                 // 16*128
    float* C    = kn + 2048;          // 16*336
    float* Km   = C + 5376;           // 16*336 (later Pi, later w)
    float* fch  = Km + 5376;          // 16*129
    float* invch= fch + 16 * 129;     // 16
    float* uS   = invch + 16;         // 16
    float* vS   = uS + 16;            // 336
    float* rsS  = vS + 336;           // 16
    float* agg  = rsS + 16;           // 2*16*128
    float* muL  = agg + 4096;         // 16
    float* rL   = muL + 16;           // 16
    float* red  = rL + 16;            // 32
    int* permS  = (int*)(red + 32);   // 128

    for (int i = tid; i < 2048; i += 256) kn[i] = g_kn[b * 2048 + i];
    if (tid < 16) { muL[tid] = g_mu[b * K_ + tid]; rL[tid] = g_r[b * K_ + tid]; }
    if (tid < 128) permS[tid] = perm[tid];
    __syncthreads();

    // cost matrix C and Kmat = exp(-C/eps)
    for (int t0 = 0; t0 < H_ / 16; t0++) {
        int hb = t0 * 16;
        for (int i = tid; i < 2048; i += 256) {
            int row = i >> 7, e = i & 127;
            fch[row * 129 + e] = g_fpos[((size_t)(b * H_ + hb + row)) * EMB_ + e];
        }
        if (tid < 16) invch[tid] = g_invn[b * H_ + hb + tid];
        __syncthreads();
        int k = tid >> 4, hh = tid & 15;
        float dot = 0.f;
#pragma unroll 8
        for (int e = 0; e < 128; e++) dot += kn[k * 128 + e] * fch[hh * 129 + e];
        int h = hb + hh;
        float cs = dot * invch[hh];
        float tt = (h + 0.5f) / (float)H_;
        float Cv = (1.f - cs) + 0.5f * fmaxf(muL[k] - tt, 0.f);
        C[k * H_ + h] = Cv;
        Km[k * H_ + h] = expf(-20.f * Cv);
        __syncthreads();
    }

    // sinkhorn
    for (int h = tid; h < H_; h += 256) vS[h] = 1.f;
    __syncthreads();
    int wid = tid >> 5, lane = tid & 31;
    for (int it = 0; it < 30; it++) {
        for (int kk = wid; kk < 16; kk += 8) {
            float s = 0.f;
            for (int h = lane; h < H_; h += 32) s += Km[kk * H_ + h] * vS[h];
            s = warpReduceSum_(s);
            if (lane == 0) uS[kk] = rL[kk] / (s + 1e-9f);
        }
        __syncthreads();
        for (int h = tid; h < H_; h += 256) {
            float s = 0.f;
#pragma unroll
            for (int k = 0; k < 16; k++) s += Km[k * H_ + h] * uS[k];
            vS[h] = (1.f / (float)H_) / (s + 1e-9f);
        }
        __syncthreads();
    }

    // Pi (in place), cot loss
    float cotl = 0.f;
    for (int i = tid; i < K_ * H_; i += 256) {
        int k = i / H_, h = i % H_;
        float p = uS[k] * Km[i] * vS[h];
        Km[i] = p;
        cotl += C[i] * p;
    }
    float cot = blockReduce256_(cotl, red);
    if (tid == 0) atomicAdd(&g_acc[1], (double)cot);
    __syncthreads();

    // row-normalize Pi -> w
    for (int kk = wid; kk < 16; kk += 8) {
        float s = 0.f;
        for (int h = lane; h < H_; h += 32) s += Km[kk * H_ + h];
        s = warpReduceSum_(s);
        if (lane == 0) rsS[kk] = s + 1e-9f;
    }
    __syncthreads();
    for (int i = tid; i < K_ * H_; i += 256) Km[i] = Km[i] / rsS[i / H_];
    __syncthreads();

    // transport-weighted aggregation (pos + rolled-weight neg1)
    {
        int e = tid & 127, kh = tid >> 7;
        float a0[8], a1[8];
#pragma unroll
        for (int kk = 0; kk < 8; kk++) { a0[kk] = 0.f; a1[kk] = 0.f; }
        const float* fp = g_fpos + (size_t)b * H_ * EMB_ + e;
        for (int h = 0; h < H_; h++) {
            float fv = fp[(size_t)h * EMB_];
            int h2 = h + SHIFT_; if (h2 >= H_) h2 -= H_;
#pragma unroll
            for (int kk = 0; kk < 8; kk++) {
                int k = kh * 8 + kk;
                a0[kk] += Km[k * H_ + h] * fv;
                a1[kk] += Km[k * H_ + h2] * fv;
            }
        }
#pragma unroll
        for (int kk = 0; kk < 8; kk++) {
            int k = kh * 8 + kk;
            agg[k * 128 + e] = a0[kk];
            agg[2048 + k * 128 + e] = a1[kk];
        }
    }
    __syncthreads();

    // similarities, log_softmax
    float dloc = 0.f;
    for (int kk = wid; kk < 16; kk += 8) {
        float np = 0.f, dp = 0.f, nn = 0.f, dn = 0.f, dq = 0.f;
#pragma unroll
        for (int j = 0; j < 4; j++) {
            int ee = lane + 32 * j;
            float kv = kn[kk * 128 + ee];
            float ap = agg[kk * 128 + ee];
            float an = agg[2048 + kk * 128 + ee];
            np += ap * ap; dp += kv * ap;
            nn += an * an; dn += kv * an;
            dq += kv * agg[kk * 128 + permS[ee]];
        }
        np = warpReduceSum_(np); dp = warpReduceSum_(dp);
        nn = warpReduceSum_(nn); dn = warpReduceSum_(dn);
        dq = warpReduceSum_(dq);
        if (lane == 0) {
            float inp = 1.f / (sqrtf(np) + 1e-8f);
            float l0 = dp * inp * (1.f / 0.07f);
            float l1 = dn / (sqrtf(nn) + 1e-8f) * (1.f / 0.07f);
            float l2 = dq * inp * (1.f / 0.07f);
            float m = fmaxf(l0, fmaxf(l1, l2));
            float lse = m + logf(expf(l0 - m) + expf(l1 - m) + expf(l2 - m));
            dloc += l0 - lse;
        }
    }
    float dsum = blockReduce256_(dloc, red);
    if (tid == 0) atomicAdd(&g_acc[2], (double)dsum);
}

// ---------------- kernel: finalize ----------------
__global__ void k_final(float* out) {
    double mse   = g_acc[0] / ((double)B_ * H_ * D_);
    double cot   = g_acc[1] / (double)B_;
    double delta = -g_acc[2] / ((double)B_ * K_);
    double ent   = -g_acc[3] / ((double)B_ * K_);
    double tv    = g_acc[4] / ((double)B_ * (K_ - 1));
    out[0] = (float)(1.0 * mse + 0.1 * cot + 0.1 * delta + 0.01 * ent + 0.01 * tv);
}

// ---------------- launch ----------------
extern "C" void kernel_launch(void* const* d_in, const int* in_sizes, int n_in,
                              void* d_out, int out_size) {
    const float* y_res    = (const float*)d_in[0];
    const float* text_emb = (const float*)d_in[1];
    const float* enc_out  = (const float*)d_in[2];
    const float* y_future = (const float*)d_in[3];
    const int*   perm     = (const int*)d_in[4];
    const float* W_t2k = (const float*)d_in[5];
    const float* b_t2k = (const float*)d_in[6];
    const float* W_kemb = (const float*)d_in[7];
    const float* b_kemb = (const float*)d_in[8];
    const float* W_tir = (const float*)d_in[9];
    const float* b_tir = (const float*)d_in[10];
    const float* var_proj = (const float*)d_in[11];
    const float* W_g1 = (const float*)d_in[12];
    const float* b_g1 = (const float*)d_in[13];
    const float* W_g2 = (const float*)d_in[14];
    const float* b_g2 = (const float*)d_in[15];
    const float* W_fp = (const float*)d_in[16];
    const float* b_fp = (const float*)d_in[17];

    cudaFuncSetAttribute(k_fpos, cudaFuncAttributeMaxDynamicSharedMemorySize, FP_SMEM);
    cudaFuncSetAttribute(k_loss, cudaFuncAttributeMaxDynamicSharedMemorySize, LOSS_SMEM);

    k_zero<<<1, 32>>>();
    k_prep_M<<<(D_ * EMB_ + 255) / 256, 256>>>(W_fp);
    k_text2k<<<B_, 128>>>(text_emb, W_t2k, b_t2k, W_kemb, b_kemb);
    k_ts<<<B_, D_>>>(enc_out);
    k_gate<<<B_ / NBG, 512>>>(text_emb, var_proj, W_g1, b_g1, W_g2, b_g2);
    k_mse<<<2688, 256>>>(y_res, y_future, W_tir, b_tir, var_proj);
    k_fpos<<<dim3(H_ / 56, B_), 256, FP_SMEM>>>(y_future, b_fp);
    k_loss<<<B_, 256, LOSS_SMEM>>>(perm);
    k_final<<<1, 1>>>((float*)d_out);
}

// round 9
// speedup vs baseline: 1.0546x; 1.0546x over previous
#include <cuda_runtime.h>
#include <math.h>
#include <stdint.h>

// ---------------- problem constants ----------------
#define B_   128
#define L_   512
#define H_   336
#define D_   256
#define TXT_ 768
#define K_   16
#define S_   4
#define EMB_ 128
#define SHIFT_ 56            // max(1, H//6)
#define PI_F 3.14159265358979323846f

// scratch (device globals; runtime allocation is forbidden). All 16B-aligned
// because several are accessed through float4*/float2*.
__device__ __align__(16) float  g_mu[B_ * K_];
__device__ __align__(16) float  g_r[B_ * K_];
__device__ __align__(16) float  g_s[B_ * H_];                 // y_tir_scalar
__device__ __align__(16) float  g_kn[B_ * K_ * EMB_];         // normalized k_emb
__device__ __align__(16) float  g_ts[B_ * D_];                // enc mean
__device__ __align__(16) float  g_tsp[B_ * 4 * D_];           // enc mean partials
__device__ __align__(16) float  g_gate[B_ * D_];
__device__ __align__(16) float  g_fpos[(size_t)B_ * H_ * EMB_];
__device__ __align__(16) float  g_invn[B_ * H_];              // 1/(||f_pos row||+1e-8)
__device__ __align__(16) float  g_Mhi[3 * D_ * EMB_];         // tf32-hi of combined W_fp
__device__ __align__(16) float  g_Mlo[3 * D_ * EMB_];         // tf32-lo of combined W_fp
__device__ __align__(16) double g_acc[8];  // 0 mse, 1 cot, 2 sum log_softmax, 3 ent, 4 tv

// ---------------- helpers ----------------
__device__ __forceinline__ float softplusf_(float x) {
    return fmaxf(x, 0.f) + log1pf(expf(-fabsf(x)));
}
__device__ __forceinline__ float sigmoidf_(float x) { return 1.f / (1.f + expf(-x)); }

__device__ __forceinline__ float tf32rn_(float x) {
    float r;
    asm("cvt.rna.tf32.f32 %0, %1;" : "=f"(r) : "f"(x));
    return r;
}

__device__ __forceinline__ float warpReduceSum_(float v) {
#pragma unroll
    for (int o = 16; o; o >>= 1) v += __shfl_xor_sync(0xffffffffu, v, o);
    return v;
}
// blockDim.x == 256, result valid on thread 0
__device__ __forceinline__ float blockReduce256_(float v, float* red) {
    int lane = threadIdx.x & 31, w = threadIdx.x >> 5;
    v = warpReduceSum_(v);
    __syncthreads();
    if (lane == 0) red[w] = v;
    __syncthreads();
    v = 0.f;
    if (w == 0) {
        v = (lane < 8) ? red[lane] : 0.f;
#pragma unroll
        for (int o = 4; o; o >>= 1) v += __shfl_xor_sync(0xffffffffu, v, o);
    }
    __syncthreads();
    return v;
}

__device__ __forceinline__ void mma_tf32_(float* c, const uint32_t* a, uint32_t b0, uint32_t b1) {
    asm volatile(
        "mma.sync.aligned.m16n8k8.row.col.f32.tf32.tf32.f32 "
        "{%0,%1,%2,%3}, {%4,%5,%6,%7}, {%8,%9}, {%0,%1,%2,%3};"
        : "+f"(c[0]), "+f"(c[1]), "+f"(c[2]), "+f"(c[3])
        : "r"(a[0]), "r"(a[1]), "r"(a[2]), "r"(a[3]), "r"(b0), "r"(b1));
}

// ---------------- kernel: zero accumulators ----------------
__global__ void k_zero() {
    if (threadIdx.x < 8) g_acc[threadIdx.x] = 0.0;
}

// ---------------- kernel: build combined Wfp matrices (tf32 hi/lo split) ----------------
// f_pos[h] = y[h]@M0 + y[h-1]@M1 + y[h-2]@M2  (y[-1]=y[-2]=y[0])
__global__ void k_prep_M(const float* __restrict__ Wfp) {
    int i = blockIdx.x * blockDim.x + threadIdx.x;
    if (i >= D_ * EMB_) return;
    float w0 = Wfp[i];
    float w1 = Wfp[D_ * EMB_ + i];
    float w2 = Wfp[2 * D_ * EMB_ + i];
    float m[3];
    m[0] = w0 + w1 + w2;
    m[1] = -(w1 + 2.f * w2);
    m[2] = w2;
#pragma unroll
    for (int j = 0; j < 3; j++) {
        float hi = tf32rn_(m[j]);
        float lo = tf32rn_(m[j] - hi);
        g_Mhi[j * D_ * EMB_ + i] = hi;
        g_Mlo[j * D_ * EMB_ + i] = lo;
    }
}

// ---------------- kernel: text2kernels + k_emb + ent/tv ----------------
__global__ void k_text2k(const float* __restrict__ text_emb,
                         const float* __restrict__ W_t2k, const float* __restrict__ b_t2k,
                         const float* __restrict__ W_kemb, const float* __restrict__ b_kemb) {
    int b = blockIdx.x, tid = threadIdx.x;
    __shared__ float temb[TXT_];
    __shared__ float raw[K_ * 7];
    __shared__ float muS[K_], sigS[K_], ampS[K_], swS[K_][S_];
    __shared__ float kap[K_ * H_];
    __shared__ float ksum[K_];
    __shared__ float kemb[K_ * EMB_];
    __shared__ float nrm[K_];
    __shared__ float entv[K_];

    for (int i = tid; i < TXT_; i += 128) temb[i] = text_emb[b * TXT_ + i];
    __syncthreads();

    if (tid < K_ * 7) {
        float acc = b_t2k[tid];
        for (int i = 0; i < TXT_; i++) acc += temb[i] * W_t2k[i * (K_ * 7) + tid];
        raw[tid] = acc;
    }
    __syncthreads();

    if (tid < K_) {
        int k = tid;
        float mu  = sigmoidf_(raw[k * 7 + 0]);
        float sig = softplusf_(raw[k * 7 + 1]) * 0.15f + 1e-3f;
        float amp = softplusf_(raw[k * 7 + 2]);
        float m = raw[k * 7 + 3];
        for (int s = 1; s < S_; s++) m = fmaxf(m, raw[k * 7 + 3 + s]);
        float es[S_], Z = 0.f;
        for (int s = 0; s < S_; s++) { es[s] = expf(raw[k * 7 + 3 + s] - m); Z += es[s]; }
        float ent = 0.f;
        for (int s = 0; s < S_; s++) {
            float sw = es[s] / Z;
            swS[k][s] = sw;
            float swc = fmaxf(sw, 1e-8f);
            ent += swc * logf(swc);
        }
        muS[k] = mu; sigS[k] = sig; ampS[k] = amp; entv[k] = ent;
        g_mu[b * K_ + k] = mu;
    }
    __syncthreads();
    if (tid == 0) {
        float tv = 0.f, es = 0.f;
        for (int k = 1; k < K_; k++) tv += fabsf(muS[k] - muS[k - 1]);
        for (int k = 0; k < K_; k++) es += entv[k];
        atomicAdd(&g_acc[3], (double)es);
        atomicAdd(&g_acc[4], (double)tv);
    }

    // kappa
    for (int i = tid; i < K_ * H_; i += 128) {
        int k = i / H_, h = i % H_;
        float t = (h + 0.5f) / (float)H_;
        float z = (t - muS[k]) / sigS[k];
        float az = fabsf(z);
        float b0 = expf(-0.5f * z * z);
        float b1 = expf(-az);
        float b2 = fmaxf(1.f - az, 0.f);
        float zc = fminf(fmaxf(z, -1.f), 1.f);
        float b3 = (az <= 1.f) ? 0.5f * (1.f + cosf(PI_F * zc)) : 0.f;
        kap[i] = ampS[k] * (b0 * swS[k][0] + b1 * swS[k][1] + b2 * swS[k][2] + b3 * swS[k][3]);
    }
    __syncthreads();

    if (tid < K_) {
        float s = 0.f;
        for (int h = 0; h < H_; h++) s += kap[tid * H_ + h];
        ksum[tid] = s + 1e-6f;
    }
    __syncthreads();
    if (tid < K_) {
        float tot = 0.f;
        for (int k = 0; k < K_; k++) tot += ksum[k];
        g_r[b * K_ + tid] = ksum[tid] / tot;
    }
    for (int h = tid; h < H_; h += 128) {
        float s = 0.f;
#pragma unroll
        for (int k = 0; k < K_; k++) s += kap[k * H_ + h];
        g_s[b * H_ + h] = s;
    }

    // k_emb = kappa @ W_kemb + b_kemb, thread = embedding column
    {
        int e = tid;
        float acc[K_];
#pragma unroll
        for (int k = 0; k < K_; k++) acc[k] = b_kemb[e];
        for (int h = 0; h < H_; h++) {
            float wv = W_kemb[h * EMB_ + e];
#pragma unroll
            for (int k = 0; k < K_; k++) acc[k] += kap[k * H_ + h] * wv;
        }
#pragma unroll
        for (int k = 0; k < K_; k++) kemb[k * EMB_ + e] = acc[k];
    }
    __syncthreads();
    {
        int w = tid >> 5, lane = tid & 31;
        for (int q = 0; q < 4; q++) {
            int k = w * 4 + q;
            float p = 0.f;
#pragma unroll
            for (int j = 0; j < 4; j++) { float v = kemb[k * EMB_ + lane + 32 * j]; p += v * v; }
            p = warpReduceSum_(p);
            if (lane == 0) nrm[k] = sqrtf(p) + 1e-8f;
        }
    }
    __syncthreads();
#pragma unroll
    for (int k = 0; k < K_; k++)
        g_kn[(b * K_ + k) * EMB_ + tid] = kemb[k * EMB_ + tid] / nrm[k];
}

// ---------------- kernels: enc_out mean over L (2-stage, deterministic) ----------------
__global__ void k_ts1(const float* __restrict__ enc) {
    int b = blockIdx.y, chunk = blockIdx.x, d = threadIdx.x;
    const float* p = enc + (size_t)b * L_ * D_ + (size_t)chunk * 128 * D_ + d;
    float s = 0.f;
#pragma unroll 8
    for (int l = 0; l < 128; l++) s += p[(size_t)l * D_];
    g_tsp[(b * 4 + chunk) * D_ + d] = s;
}
__global__ void k_ts2() {
    int b = blockIdx.x, d = threadIdx.x;
    float s = g_tsp[(b * 4 + 0) * D_ + d] + g_tsp[(b * 4 + 1) * D_ + d]
            + g_tsp[(b * 4 + 2) * D_ + d] + g_tsp[(b * 4 + 3) * D_ + d];
    g_ts[b * D_ + d] = s * (1.f / (float)L_);
}

// ---------------- kernel: gate MLP ----------------
#define NBG 4
__global__ void k_gate(const float* __restrict__ text_emb, const float* __restrict__ var_proj,
                       const float* __restrict__ Wg1, const float* __restrict__ bg1,
                       const float* __restrict__ Wg2, const float* __restrict__ bg2) {
    int b0 = blockIdx.x * NBG, tid = threadIdx.x; // 512 threads
    __shared__ float gin[NBG][2 * D_ + TXT_];
    __shared__ float h1[NBG][512];
    for (int bb = 0; bb < NBG; bb++) {
        int b = b0 + bb;
        for (int i = tid; i < D_; i += 512) gin[bb][i] = g_ts[b * D_ + i];
        for (int i = tid; i < TXT_; i += 512) gin[bb][D_ + i] = text_emb[b * TXT_ + i];
        for (int i = tid; i < D_; i += 512) gin[bb][D_ + TXT_ + i] = var_proj[i];
    }
    __syncthreads();
    {
        int j = tid;
        float a[NBG];
#pragma unroll
        for (int bb = 0; bb < NBG; bb++) a[bb] = bg1[j];
        for (int i = 0; i < 2 * D_ + TXT_; i++) {
            float w = Wg1[i * 512 + j];
#pragma unroll
            for (int bb = 0; bb < NBG; bb++) a[bb] += gin[bb][i] * w;
        }
#pragma unroll
        for (int bb = 0; bb < NBG; bb++) h1[bb][j] = fmaxf(a[bb], 0.f);
    }
    __syncthreads();
    if (tid < D_) {
        int d = tid;
        float a[NBG];
#pragma unroll
        for (int bb = 0; bb < NBG; bb++) a[bb] = bg2[d];
        for (int i = 0; i < 512; i++) {
            float w = Wg2[i * D_ + d];
#pragma unroll
            for (int bb = 0; bb < NBG; bb++) a[bb] += h1[bb][i] * w;
        }
#pragma unroll
        for (int bb = 0; bb < NBG; bb++) g_gate[(b0 + bb) * D_ + d] = sigmoidf_(a[bb]);
    }
}

// ---------------- kernel: fused y_tir/gate/mse ----------------
__global__ void k_mse(const float* __restrict__ y_res, const float* __restrict__ y_fut,
                      const float* __restrict__ W_tir, const float* __restrict__ b_tir,
                      const float* __restrict__ var_proj) {
    __shared__ float red[32];
    const int N4 = B_ * H_ * (D_ / 4);
    float local = 0.f;
    for (int i4 = blockIdx.x * blockDim.x + threadIdx.x; i4 < N4; i4 += gridDim.x * blockDim.x) {
        int b = i4 / (H_ * (D_ / 4));
        int rem = i4 % (H_ * (D_ / 4));
        int h = rem / (D_ / 4);
        int d4 = rem % (D_ / 4);
        float4 yr = *(const float4*)&y_res[(size_t)i4 * 4];
        float4 yf = *(const float4*)&y_fut[(size_t)i4 * 4];
        float4 wt = *(const float4*)&W_tir[d4 * 4];
        float4 bt = *(const float4*)&b_tir[d4 * 4];
        float4 vp = *(const float4*)&var_proj[d4 * 4];
        float4 gt = *(const float4*)&g_gate[b * D_ + d4 * 4];
        float s = g_s[b * H_ + h];
        float dx, ytir;
        ytir = (s * wt.x + bt.x) * vp.x; dx = (yr.x + 0.5f * gt.x * (ytir - yr.x)) - yf.x; local += dx * dx;
        ytir = (s * wt.y + bt.y) * vp.y; dx = (yr.y + 0.5f * gt.y * (ytir - yr.y)) - yf.y; local += dx * dx;
        ytir = (s * wt.z + bt.z) * vp.z; dx = (yr.z + 0.5f * gt.z * (ytir - yr.z)) - yf.z; local += dx * dx;
        ytir = (s * wt.w + bt.w) * vp.w; dx = (yr.w + 0.5f * gt.w * (ytir - yr.w)) - yf.w; local += dx * dx;
    }
    float tot = blockReduce256_(local, red);
    if (threadIdx.x == 0) atomicAdd(&g_acc[0], (double)tot);
}

// ---------------- kernel: f_pos GEMM on tensor cores (tf32 3x split) ----------------
// tile: 128 h-rows x 128 emb per CTA; 512 threads = 8 row-warps x 2 col-warps.
// C[h] = sum_j y[h-j] @ M_j, three A bases into a 130-row shared y tile.
#define HT     128
#define KC     16
#define YROWS  130
#define YSTR   20
#define MSTR   136
#define YSH_FLOATS (2 * YROWS * YSTR)            // 5200
#define MSH_FLOATS (3 * 2 * KC * MSTR)           // 13056
#define SRED_FLOATS (HT * 2)                     // 256
#define FP_SMEM ((YSH_FLOATS + MSH_FLOATS + SRED_FLOATS) * 4)

__global__ __launch_bounds__(512, 1)
void k_fpos_tc(const float* __restrict__ yf, const float* __restrict__ bfp) {
    extern __shared__ float sm[];
    float* ysh  = sm;                         // [2][130][20]  hi then lo
    float* Msh  = sm + YSH_FLOATS;            // [3][2][16][136]
    float* sred = sm + YSH_FLOATS + MSH_FLOATS; // [128][2]

    int b = blockIdx.y;
    int h0 = blockIdx.x * HT;
    int tid = threadIdx.x;
    int warp = tid >> 5, lane = tid & 31;
    int r = warp >> 1, c = warp & 1;          // row-group, col-half
    int wr = r * 16;
    int n_base = c * 64;
    int q = lane >> 2, qq = lane & 3;

    float acc[8][4];
#pragma unroll
    for (int nt = 0; nt < 8; nt++)
#pragma unroll
        for (int i = 0; i < 4; i++) acc[nt][i] = 0.f;

    for (int kc = 0; kc < D_ / KC; kc++) {
        // ---- load y tile (rows h0-2 .. h0+127, cols kc*16..+16), hi/lo split ----
        {
            const float* yb = yf + (size_t)b * H_ * D_ + kc * KC;
            for (int i = tid; i < YROWS * KC; i += 512) {
                int row = i >> 4, col = i & 15;
                int h = h0 - 2 + row;
                h = max(0, min(h, H_ - 1));
                float x = yb[(size_t)h * D_ + col];
                float hi = tf32rn_(x);
                float lo = tf32rn_(x - hi);
                ysh[row * YSTR + col] = hi;
                ysh[YROWS * YSTR + row * YSTR + col] = lo;
            }
        }
        // ---- load M chunk (3 shifts x hi/lo x 16 k x 128 e) ----
        {
            int base_g = kc * KC * EMB_;
            for (int i = tid; i < 3 * KC * EMB_; i += 512) {
                int j = i / (KC * EMB_);
                int rem = i - j * (KC * EMB_);
                int k = rem >> 7, e = rem & 127;
                int gidx = j * D_ * EMB_ + base_g + k * EMB_ + e;
                Msh[((j * 2 + 0) * KC + k) * MSTR + e] = g_Mhi[gidx];
                Msh[((j * 2 + 1) * KC + k) * MSTR + e] = g_Mlo[gidx];
            }
        }
        __syncthreads();

#pragma unroll
        for (int kk = 0; kk < KC; kk += 8) {
            uint32_t Ah[3][4], Al[3][4];
#pragma unroll
            for (int j = 0; j < 3; j++) {
                int base = wr + 2 - j;
                int r0 = (base + q) * YSTR, r1 = (base + q + 8) * YSTR;
                int c0 = kk + qq, c1 = kk + qq + 4;
                Ah[j][0] = __float_as_uint(ysh[r0 + c0]);
                Ah[j][1] = __float_as_uint(ysh[r1 + c0]);
                Ah[j][2] = __float_as_uint(ysh[r0 + c1]);
                Ah[j][3] = __float_as_uint(ysh[r1 + c1]);
                Al[j][0] = __float_as_uint(ysh[YROWS * YSTR + r0 + c0]);
                Al[j][1] = __float_as_uint(ysh[YROWS * YSTR + r1 + c0]);
                Al[j][2] = __float_as_uint(ysh[YROWS * YSTR + r0 + c1]);
                Al[j][3] = __float_as_uint(ysh[YROWS * YSTR + r1 + c1]);
            }
#pragma unroll
            for (int nt = 0; nt < 8; nt++) {
                int n = n_base + nt * 8 + q;
#pragma unroll
                for (int j = 0; j < 3; j++) {
                    const float* Mj = &Msh[(j * 2) * KC * MSTR];
                    const float* MjL = Mj + KC * MSTR;
                    uint32_t bh0 = __float_as_uint(Mj[(kk + qq) * MSTR + n]);
                    uint32_t bh1 = __float_as_uint(Mj[(kk + qq + 4) * MSTR + n]);
                    uint32_t bl0 = __float_as_uint(MjL[(kk + qq) * MSTR + n]);
                    uint32_t bl1 = __float_as_uint(MjL[(kk + qq + 4) * MSTR + n]);
                    mma_tf32_(acc[nt], Ah[j], bh0, bh1);
                    mma_tf32_(acc[nt], Ah[j], bl0, bl1);
                    mma_tf32_(acc[nt], Al[j], bh0, bh1);
                }
            }
        }
        __syncthreads();
    }

    // ---- epilogue: bias, store, row norms ----
    float ss0 = 0.f, ss1 = 0.f;
    int h_lo = h0 + wr + q, h_hi = h_lo + 8;
#pragma unroll
    for (int nt = 0; nt < 8; nt++) {
        int e = n_base + nt * 8 + 2 * qq;
        float b0f = bfp[e], b1f = bfp[e + 1];
        float v0 = acc[nt][0] + b0f, v1 = acc[nt][1] + b1f;
        float v2 = acc[nt][2] + b0f, v3 = acc[nt][3] + b1f;
        ss0 += v0 * v0 + v1 * v1;
        ss1 += v2 * v2 + v3 * v3;
        if (h_lo < H_) {
            float2 o; o.x = v0; o.y = v1;
            *(float2*)&g_fpos[((size_t)(b * H_ + h_lo)) * EMB_ + e] = o;
        }
        if (h_hi < H_) {
            float2 o; o.x = v2; o.y = v3;
            *(float2*)&g_fpos[((size_t)(b * H_ + h_hi)) * EMB_ + e] = o;
        }
    }
    ss0 += __shfl_xor_sync(0xffffffffu, ss0, 1);
    ss0 += __shfl_xor_sync(0xffffffffu, ss0, 2);
    ss1 += __shfl_xor_sync(0xffffffffu, ss1, 1);
    ss1 += __shfl_xor_sync(0xffffffffu, ss1, 2);
    if (qq == 0) {
        sred[(wr + q) * 2 + c] = ss0;
        sred[(wr + q + 8) * 2 + c] = ss1;
    }
    __syncthreads();
    if (tid < HT) {
        int h = h0 + tid;
        if (h < H_) {
            float ss = sred[tid * 2] + sred[tid * 2 + 1];
            g_invn[b * H_ + h] = 1.f / (sqrtf(ss) + 1e-8f);
        }
    }
}

// ---------------- kernel: per-batch cost/sinkhorn/contrastive ----------------
#define LS_FLOATS (2048 + 5376 + 5376 + 16 * 129 + 16 + 16 + 336 + 16 + 4096 + 16 + 16 + 32)
#define LOSS_SMEM (LS_FLOATS * 4 + 128 * 4)
__global__ void k_loss(const int* __restrict__ perm) {
    int b = blockIdx.x, tid = threadIdx.x; // 256 threads
    extern __shared__ float sm[];
    float* kn   = sm;                 // 16*128
    float* C    = kn + 2048;          // 16*336
    float* Km   = C + 5376;           // 16*336 (later Pi, later w)
    float* fch  = Km + 5376;          // 16*129
    float* invch= fch + 16 * 129;     // 16
    float* uS   = invch + 16;         // 16
    float* vS   = uS + 16;            // 336
    float* rsS  = vS + 336;           // 16
    float* agg  = rsS + 16;           // 2*16*128
    float* muL  = agg + 4096;         // 16
    float* rL   = muL + 16;           // 16
    float* red  = rL + 16;            // 32
    int* permS  = (int*)(red + 32);   // 128

    for (int i = tid; i < 2048; i += 256) kn[i] = g_kn[b * 2048 + i];
    if (tid < 16) { muL[tid] = g_mu[b * K_ + tid]; rL[tid] = g_r[b * K_ + tid]; }
    if (tid < 128) permS[tid] = perm[tid];
    __syncthreads();

    // cost matrix C and Kmat = exp(-C/eps)
    for (int t0 = 0; t0 < H_ / 16; t0++) {
        int hb = t0 * 16;
        for (int i = tid; i < 2048; i += 256) {
            int row = i >> 7, e = i & 127;
            fch[row * 129 + e] = g_fpos[((size_t)(b * H_ + hb + row)) * EMB_ + e];
        }
        if (tid < 16) invch[tid] = g_invn[b * H_ + hb + tid];
        __syncthreads();
        int k = tid >> 4, hh = tid & 15;
        float dot = 0.f;
#pragma unroll 8
        for (int e = 0; e < 128; e++) dot += kn[k * 128 + e] * fch[hh * 129 + e];
        int h = hb + hh;
        float cs = dot * invch[hh];
        float tt = (h + 0.5f) / (float)H_;
        float Cv = (1.f - cs) + 0.5f * fmaxf(muL[k] - tt, 0.f);
        C[k * H_ + h] = Cv;
        Km[k * H_ + h] = expf(-20.f * Cv);
        __syncthreads();
    }

    // sinkhorn
    for (int h = tid; h < H_; h += 256) vS[h] = 1.f;
    __syncthreads();
    int wid = tid >> 5, lane = tid & 31;
    for (int it = 0; it < 30; it++) {
        for (int kk = wid; kk < 16; kk += 8) {
            float s = 0.f;
            for (int h = lane; h < H_; h += 32) s += Km[kk * H_ + h] * vS[h];
            s = warpReduceSum_(s);
            if (lane == 0) uS[kk] = rL[kk] / (s + 1e-9f);
        }
        __syncthreads();
        for (int h = tid; h < H_; h += 256) {
            float s = 0.f;
#pragma unroll
            for (int k = 0; k < 16; k++) s += Km[k * H_ + h] * uS[k];
            vS[h] = (1.f / (float)H_) / (s + 1e-9f);
        }
        __syncthreads();
    }

    // Pi (in place), cot loss
    float cotl = 0.f;
    for (int i = tid; i < K_ * H_; i += 256) {
        int k = i / H_, h = i % H_;
        float p = uS[k] * Km[i] * vS[h];
        Km[i] = p;
        cotl += C[i] * p;
    }
    float cot = blockReduce256_(cotl, red);
    if (tid == 0) atomicAdd(&g_acc[1], (double)cot);
    __syncthreads();

    // row-normalize Pi -> w
    for (int kk = wid; kk < 16; kk += 8) {
        float s = 0.f;
        for (int h = lane; h < H_; h += 32) s += Km[kk * H_ + h];
        s = warpReduceSum_(s);
        if (lane == 0) rsS[kk] = s + 1e-9f;
    }
    __syncthreads();
    for (int i = tid; i < K_ * H_; i += 256) Km[i] = Km[i] / rsS[i / H_];
    __syncthreads();

    // transport-weighted aggregation (pos + rolled-weight neg1)
    {
        int e = tid & 127, kh = tid >> 7;
        float a0[8], a1[8];
#pragma unroll
        for (int kk = 0; kk < 8; kk++) { a0[kk] = 0.f; a1[kk] = 0.f; }
        const float* fp = g_fpos + (size_t)b * H_ * EMB_ + e;
        for (int h = 0; h < H_; h++) {
            float fv = fp[(size_t)h * EMB_];
            int h2 = h + SHIFT_; if (h2 >= H_) h2 -= H_;
#pragma unroll
            for (int kk = 0; kk < 8; kk++) {
                int k = kh * 8 + kk;
                a0[kk] += Km[k * H_ + h] * fv;
                a1[kk] += Km[k * H_ + h2] * fv;
            }
        }
#pragma unroll
        for (int kk = 0; kk < 8; kk++) {
            int k = kh * 8 + kk;
            agg[k * 128 + e] = a0[kk];
            agg[2048 + k * 128 + e] = a1[kk];
        }
    }
    __syncthreads();

    // similarities, log_softmax
    float dloc = 0.f;
    for (int kk = wid; kk < 16; kk += 8) {
        float np = 0.f, dp = 0.f, nn = 0.f, dn = 0.f, dq = 0.f;
#pragma unroll
        for (int j = 0; j < 4; j++) {
            int ee = lane + 32 * j;
            float kv = kn[kk * 128 + ee];
            float ap = agg[kk * 128 + ee];
            float an = agg[2048 + kk * 128 + ee];
            np += ap * ap; dp += kv * ap;
            nn += an * an; dn += kv * an;
            dq += kv * agg[kk * 128 + permS[ee]];
        }
        np = warpReduceSum_(np); dp = warpReduceSum_(dp);
        nn = warpReduceSum_(nn); dn = warpReduceSum_(dn);
        dq = warpReduceSum_(dq);
        if (lane == 0) {
            float inp = 1.f / (sqrtf(np) + 1e-8f);
            float l0 = dp * inp * (1.f / 0.07f);
            float l1 = dn / (sqrtf(nn) + 1e-8f) * (1.f / 0.07f);
            float l2 = dq * inp * (1.f / 0.07f);
            float m = fmaxf(l0, fmaxf(l1, l2));
            float lse = m + logf(expf(l0 - m) + expf(l1 - m) + expf(l2 - m));
            dloc += l0 - lse;
        }
    }
    float dsum = blockReduce256_(dloc, red);
    if (tid == 0) atomicAdd(&g_acc[2], (double)dsum);
}

// ---------------- kernel: finalize ----------------
__global__ void k_final(float* out) {
    double mse   = g_acc[0] / ((double)B_ * H_ * D_);
    double cot   = g_acc[1] / (double)B_;
    double delta = -g_acc[2] / ((double)B_ * K_);
    double ent   = -g_acc[3] / ((double)B_ * K_);
    double tv    = g_acc[4] / ((double)B_ * (K_ - 1));
    out[0] = (float)(1.0 * mse + 0.1 * cot + 0.1 * delta + 0.01 * ent + 0.01 * tv);
}

// ---------------- launch ----------------
extern "C" void kernel_launch(void* const* d_in, const int* in_sizes, int n_in,
                              void* d_out, int out_size) {
    const float* y_res    = (const float*)d_in[0];
    const float* text_emb = (const float*)d_in[1];
    const float* enc_out  = (const float*)d_in[2];
    const float* y_future = (const float*)d_in[3];
    const int*   perm     = (const int*)d_in[4];
    const float* W_t2k = (const float*)d_in[5];
    const float* b_t2k = (const float*)d_in[6];
    const float* W_kemb = (const float*)d_in[7];
    const float* b_kemb = (const float*)d_in[8];
    const float* W_tir = (const float*)d_in[9];
    const float* b_tir = (const float*)d_in[10];
    const float* var_proj = (const float*)d_in[11];
    const float* W_g1 = (const float*)d_in[12];
    const float* b_g1 = (const float*)d_in[13];
    const float* W_g2 = (const float*)d_in[14];
    const float* b_g2 = (const float*)d_in[15];
    const float* W_fp = (const float*)d_in[16];
    const float* b_fp = (const float*)d_in[17];

    cudaFuncSetAttribute(k_fpos_tc, cudaFuncAttributeMaxDynamicSharedMemorySize, FP_SMEM);
    cudaFuncSetAttribute(k_loss, cudaFuncAttributeMaxDynamicSharedMemorySize, LOSS_SMEM);

    k_zero<<<1, 32>>>();
    k_prep_M<<<(D_ * EMB_ + 255) / 256, 256>>>(W_fp);
    k_text2k<<<B_, 128>>>(text_emb, W_t2k, b_t2k, W_kemb, b_kemb);
    k_ts1<<<dim3(4, B_), D_>>>(enc_out);
    k_ts2<<<B_, D_>>>();
    k_gate<<<B_ / NBG, 512>>>(text_emb, var_proj, W_g1, b_g1, W_g2, b_g2);
    k_mse<<<2688, 256>>>(y_res, y_future, W_tir, b_tir, var_proj);
    k_fpos_tc<<<dim3((H_ + HT - 1) / HT, B_), 512, FP_SMEM>>>(y_future, b_fp);
    k_loss<<<B_, 256, LOSS_SMEM>>>(perm);
    k_final<<<1, 1>>>((float*)d_out);
}